// round 16
// baseline (speedup 1.0000x reference)
#include <cuda_runtime.h>
#include <cuda_bf16.h>
#include <math.h>

#define Bb 16
#define Nn 4096
#define Dd 64
#define Ss 1024
#define Kk 32
#define Mm (Bb*Ss*Kk)

typedef unsigned long long ull;
typedef unsigned int u32;
typedef unsigned short u16;

__device__ int    g_knn[Mm];
__device__ float  g_y0[Mm*64];
__device__ float  g_y1[Mm*64];
__device__ float  g_parts[4096*128];
__device__ float  g_partq[4096*128];
__device__ float  g_gmax[Bb*Ss*128];
__device__ float  g_scale[128];
__device__ float  g_shift[128];
__device__ __align__(16) u16 g_Bh[3][8192];
__device__ __align__(16) u16 g_Bl[3][8192];
__device__ float  g_W0xyz[192];
__device__ int    g_dummy;

// ---- f32x2 helpers (fps) ----
__device__ __forceinline__ ull f2add(ull a, ull b){ ull d; asm("add.rn.f32x2 %0,%1,%2;":"=l"(d):"l"(a),"l"(b)); return d; }
__device__ __forceinline__ ull f2mul(ull a, ull b){ ull d; asm("mul.rn.f32x2 %0,%1,%2;":"=l"(d):"l"(a),"l"(b)); return d; }
__device__ __forceinline__ ull f2dup(float v){ ull d; asm("mov.b64 %0,{%1,%1};":"=l"(d):"f"(v)); return d; }
__device__ __forceinline__ ull f2pack(float l, float h){ ull d; asm("mov.b64 %0,{%1,%2};":"=l"(d):"f"(l),"f"(h)); return d; }
__device__ __forceinline__ void f2unpack(ull v, float& l, float& h){ asm("mov.b64 {%0,%1},%2;":"=f"(l),"=f"(h):"l"(v)); }
__device__ __forceinline__ unsigned mono(float f){ unsigned b=__float_as_uint(f); return b ^ (unsigned)(((int)b>>31)|0x80000000); }

__device__ __forceinline__ u32 bfpack(float a, float b){
    __nv_bfloat16 ha=__float2bfloat16(a), hb=__float2bfloat16(b);
    return (u32)(*(u16*)&ha) | ((u32)(*(u16*)&hb)<<16);
}
__device__ __forceinline__ u32 s2u(const void* p){
    u32 a; asm("{ .reg .u64 t; cvta.to.shared.u64 t, %1; cvt.u32.u64 %0, t; }":"=r"(a):"l"(p)); return a;
}

#define MMA_BF16(c, a, b0v, b1v) \
    asm volatile("mma.sync.aligned.m16n8k16.row.col.f32.bf16.bf16.f32 " \
        "{%0,%1,%2,%3},{%4,%5,%6,%7},{%8,%9},{%0,%1,%2,%3};" \
        : "+f"((c)[0]),"+f"((c)[1]),"+f"((c)[2]),"+f"((c)[3]) \
        : "r"((a)[0]),"r"((a)[1]),"r"((a)[2]),"r"((a)[3]), "r"(b0v),"r"(b1v))

#define LDSM_X4(r0,r1,r2,r3,addr) \
    asm volatile("ldmatrix.sync.aligned.m8n8.x4.shared.b16 {%0,%1,%2,%3}, [%4];" \
        : "=r"(r0),"=r"(r1),"=r"(r2),"=r"(r3) : "r"(addr))

// ============================================================================
// 0) prep + dummies (capture slot 3 = fps)
// ============================================================================
__device__ __forceinline__ void wsplit(float x, u16* H, u16* L, int o, int k){
    __nv_bfloat16 h = __float2bfloat16(x);
    float r = x - __bfloat162float(h);
    __nv_bfloat16 l = __float2bfloat16(r);
    u32 off = (u32)(o*128) + (((u32)(k*2)) ^ (u32)((o&7)<<4));
    H[off>>1] = *(u16*)&h;  L[off>>1] = *(u16*)&l;
}
__global__ void prep_kernel(const float* __restrict__ W0, const float* __restrict__ W1,
                            const float* __restrict__ W2){
    int t = blockIdx.x*256+threadIdx.x, st = gridDim.x*256;
    for (int i=t;i<4096;i+=st){ int o=i>>6,k=i&63; wsplit(W0[o*67+3+k], g_Bh[0], g_Bl[0], o,k); }
    for (int i=t;i<4096;i+=st){ int o=i>>6,k=i&63; wsplit(W1[o*64+k],   g_Bh[1], g_Bl[1], o,k); }
    for (int i=t;i<8192;i+=st){ int o=i>>6,k=i&63; wsplit(W2[o*64+k],   g_Bh[2], g_Bl[2], o,k); }
    for (int i=t;i<192;i+=st){ int j=i>>6,o=i&63; g_W0xyz[j*64+o] = W0[o*67+j]; }
}
__global__ void dummy_kernel(){ if (threadIdx.x == 1024) g_dummy = 1; }

// ============================================================================
// 1) FPS: 1024 threads x 4 points (2 f32x2 pairs). Bit-exact; 1 barrier/iter.
// ============================================================================
__global__ __launch_bounds__(1024, 1)
void fps_kernel(const float* __restrict__ xyz, float* __restrict__ out_xyz)
{
    extern __shared__ float4 sp[];
    ull* s_key = (ull*)(sp + Nn);                  // [2][32]
    const int b = blockIdx.x, tid = threadIdx.x;
    const int lane = tid & 31, warp = tid >> 5;
    const float* base = xyz + (size_t)b * Nn * 3;

    ull px2[2], py2[2], pz2[2];
    float dist[4];
#pragma unroll
    for (int j = 0; j < 2; j++) {
        int plo = tid + (2*j)*1024, phi = tid + (2*j+1)*1024;
        float Xl = base[plo*3+0], Yl = base[plo*3+1], Zl = base[plo*3+2];
        float Xh = base[phi*3+0], Yh = base[phi*3+1], Zh = base[phi*3+2];
        sp[plo] = make_float4(Xl, Yl, Zl, 0.f);
        sp[phi] = make_float4(Xh, Yh, Zh, 0.f);
        px2[j] = f2pack(Xl, Xh); py2[j] = f2pack(Yl, Yh); pz2[j] = f2pack(Zl, Zh);
        dist[2*j] = 1e10f; dist[2*j+1] = 1e10f;
    }
    __syncthreads();

    int far = 0;
    float* ob = out_xyz + (size_t)b * Ss * 3;
    for (int it = 0; it < Ss; ++it) {
        float4 c = sp[far];
        if (tid == 0) { ob[it*3+0]=c.x; ob[it*3+1]=c.y; ob[it*3+2]=c.z; }
        ull ncx = f2dup(-c.x), ncy = f2dup(-c.y), ncz = f2dup(-c.z);
        unsigned u[4];
#pragma unroll
        for (int j = 0; j < 2; j++) {
            ull dx = f2add(px2[j], ncx), dy = f2add(py2[j], ncy), dz = f2add(pz2[j], ncz);
            ull s = f2add(f2add(f2mul(dx,dx), f2mul(dy,dy)), f2mul(dz,dz));
            float lo, hi; f2unpack(s, lo, hi);
            float dl = fminf(dist[2*j], lo), dh = fminf(dist[2*j+1], hi);
            dist[2*j] = dl; dist[2*j+1] = dh;
            u[2*j] = __float_as_uint(dl); u[2*j+1] = __float_as_uint(dh);
        }
        // depth-2 tree argmax over 4 (strict > keeps lower slot on ties)
        bool ga = u[1] > u[0];
        unsigned v01 = ga ? u[1] : u[0]; unsigned j01 = ga ? 1u : 0u;
        bool gb = u[3] > u[2];
        unsigned v23 = gb ? u[3] : u[2]; unsigned j23 = gb ? 3u : 2u;
        bool gc = v23 > v01;
        unsigned bb = gc ? v23 : v01;    unsigned jj = gc ? j23 : j01;
        int bi = tid + (int)jj * 1024;

        unsigned mv = __reduce_max_sync(0xffffffffu, bb);
        int ci = (bb == mv) ? bi : 0x7fffffff;
        int mi = __reduce_min_sync(0xffffffffu, ci);
        if (lane == 0)
            s_key[(it&1)*32 + warp] = ((ull)mv << 32) | (unsigned)(0x7fffffff - mi);
        __syncthreads();
        ull k = s_key[(it&1)*32 + lane];
        unsigned hv = (unsigned)(k >> 32), lv = (unsigned)k;
        unsigned mh = __reduce_max_sync(0xffffffffu, hv);
        unsigned ml = __reduce_max_sync(0xffffffffu, (hv == mh) ? lv : 0u);
        far = 0x7fffffff - (int)ml;
    }
}

// ============================================================================
// 2) KNN (unchanged): warp per query, single pass
// ============================================================================
__global__ __launch_bounds__(512, 1)
void knn_kernel(const float* __restrict__ xyz, const float* __restrict__ samp)
{
    extern __shared__ float4 sq[];
    const int b = blockIdx.y, t = threadIdx.x;
    const int lane = t & 31, w = t >> 5;
    const float* base = xyz + (size_t)b * Nn * 3;
    for (int j = t; j < Nn; j += 512) {
        float x = base[j*3], y = base[j*3+1], z = base[j*3+2];
        sq[j] = make_float4(x, y, z, fmaf(x,x, fmaf(y,y, z*z)));
    }
    __syncthreads();

    const int q = b * Ss + blockIdx.x * 16 + w;
    float qx = samp[q*3], qy = samp[q*3+1], qz = samp[q*3+2];
    float ax = -2.0f*qx, ay = -2.0f*qy, az = -2.0f*qz;

    float4 p0 = sq[lane];
    unsigned held = mono(fmaf(az, p0.z, fmaf(ay, p0.y, fmaf(ax, p0.x, p0.w))));
    int held_idx = lane;
    unsigned thr = __reduce_max_sync(0xffffffffu, held);

#pragma unroll 1
    for (int step = 1; step < Nn/32; step++) {
        float4 p = sq[step*32 + lane];
        unsigned u = mono(fmaf(az, p.z, fmaf(ay, p.y, fmaf(ax, p.x, p.w))));
        unsigned m = __ballot_sync(0xffffffffu, u < thr);
        while (m) {
            int src = __ffs(m) - 1;
            unsigned uc = __shfl_sync(0xffffffffu, u, src);
            if (uc < thr) {
                unsigned vb = __ballot_sync(0xffffffffu, held == thr);
                int victim = __ffs(vb) - 1;
                if (lane == victim) { held = uc; held_idx = step*32 + src; }
                thr = __reduce_max_sync(0xffffffffu, held);
            }
            m &= m - 1;
            m &= __ballot_sync(0xffffffffu, u < thr);
        }
    }
    g_knn[(size_t)q * Kk + lane] = held_idx;
}

// ============================================================================
// 3) MLP layer (R13 config: 128 threads, 4 warps x 32-row tiles).
//    LAYER 2: single pass, both 64-ch B halves resident, A built once.
// ============================================================================
template <int LAYER>
__global__ __launch_bounds__(128)
void mma_kernel(const float* __restrict__ fea, const float* __restrict__ xyz,
                const float* __restrict__ samp)
{
    constexpr int NB    = (LAYER==2) ? 128 : 64;
    constexpr int NHALF = NB/64;
    constexpr int A_HI=0, A_LO=16384, B_HI=32768;
    constexpr int B_LO = B_HI + NB*128;
    constexpr int SCR  = (LAYER==2) ? (B_LO + NB*128) : 0;   // L2: scratch above B
    constexpr int DX=49152, WX=50688, IDX=51456;             // layer0 only

    extern __shared__ __align__(16) char sm[];
    const int t = threadIdx.x, lane = t&31, w = t>>5;
    const int m0p = blockIdx.x*128;

    {
        const uint4* BH = (const uint4*)(g_Bh[LAYER]);
        const uint4* BL = (const uint4*)(g_Bl[LAYER]);
        uint4* dh = (uint4*)(sm+B_HI); uint4* dl = (uint4*)(sm+B_LO);
        for (int i = t; i < NB*8; i += 128) { dh[i] = BH[i]; dl[i] = BL[i]; }
    }

    const int rloc0 = w*32 + (lane>>4);
    const int cc = (lane & 15)*4;
    if (LAYER == 0) {
        int m = m0p + t, g = m>>5, idx = g_knn[m];
        int row = (g>>10)*Nn + idx;
        ((int*)(sm+IDX))[t] = row;
        ((float*)(sm+DX))[t]     = xyz[row*3+0]-samp[g*3+0];
        ((float*)(sm+DX))[128+t] = xyz[row*3+1]-samp[g*3+1];
        ((float*)(sm+DX))[256+t] = xyz[row*3+2]-samp[g*3+2];
        for (int i=t;i<192;i+=128) ((float*)(sm+WX))[i] = g_W0xyz[i];
        __syncthreads();
#pragma unroll 4
        for (int it2 = 0; it2 < 16; it2++) {
            int rr = rloc0 + it2*2;
            int gr = ((const int*)(sm+IDX))[rr];
            float4 v = *(const float4*)(fea + (size_t)gr*Dd + cc);
            u32 sw = (u32)((rr&7)<<4);
            __nv_bfloat16 h0=__float2bfloat16(v.x), h1=__float2bfloat16(v.y);
            __nv_bfloat16 h2=__float2bfloat16(v.z), h3=__float2bfloat16(v.w);
            u32 o0 = ((u32)(cc*2)) ^ sw;
            *(u32*)(sm+A_HI + rr*128 + o0)   = (u32)(*(u16*)&h0) | ((u32)(*(u16*)&h1)<<16);
            *(u32*)(sm+A_HI + rr*128 + o0+4) = (u32)(*(u16*)&h2) | ((u32)(*(u16*)&h3)<<16);
            *(u32*)(sm+A_LO + rr*128 + o0)   = bfpack(v.x-__bfloat162float(h0), v.y-__bfloat162float(h1));
            *(u32*)(sm+A_LO + rr*128 + o0+4) = bfpack(v.z-__bfloat162float(h2), v.w-__bfloat162float(h3));
        }
    } else {
        const float* Xin = (LAYER==1) ? g_y0 : g_y1;
        const float sc0 = g_scale[cc],   sh0 = g_shift[cc];
        const float sc1 = g_scale[cc+1], sh1 = g_shift[cc+1];
        const float sc2 = g_scale[cc+2], sh2 = g_shift[cc+2];
        const float sc3 = g_scale[cc+3], sh3 = g_shift[cc+3];
#pragma unroll 4
        for (int it2 = 0; it2 < 16; it2++) {
            int rr = rloc0 + it2*2;
            float4 v = *(const float4*)(Xin + (size_t)(m0p+rr)*64 + cc);
            float x0 = fmaxf(fmaf(v.x, sc0, sh0), 0.f);
            float x1 = fmaxf(fmaf(v.y, sc1, sh1), 0.f);
            float x2 = fmaxf(fmaf(v.z, sc2, sh2), 0.f);
            float x3 = fmaxf(fmaf(v.w, sc3, sh3), 0.f);
            u32 sw = (u32)((rr&7)<<4);
            __nv_bfloat16 h0=__float2bfloat16(x0), h1=__float2bfloat16(x1);
            __nv_bfloat16 h2=__float2bfloat16(x2), h3=__float2bfloat16(x3);
            u32 o0 = ((u32)(cc*2)) ^ sw;
            *(u32*)(sm+A_HI + rr*128 + o0)   = (u32)(*(u16*)&h0) | ((u32)(*(u16*)&h1)<<16);
            *(u32*)(sm+A_HI + rr*128 + o0+4) = (u32)(*(u16*)&h2) | ((u32)(*(u16*)&h3)<<16);
            *(u32*)(sm+A_LO + rr*128 + o0)   = bfpack(x0-__bfloat162float(h0), x1-__bfloat162float(h1));
            *(u32*)(sm+A_LO + rr*128 + o0+4) = bfpack(x2-__bfloat162float(h2), x3-__bfloat162float(h3));
        }
    }
    __syncthreads();

    const u32 sbase = s2u(sm);
    const int qr = lane>>2, qc = lane&3;
    const u32 aRowSel = (u32)(((lane>>3)&1)*8 + (lane&7));
    const u32 aKSel   = (u32)((lane>>4)*16);
    const u32 bNSel   = (u32)((lane>>4)*8 + (lane&7));
    const u32 bKSel   = (u32)(((lane>>3)&1)*16);

    float* Ssm = (float*)(sm + SCR);
    float* Sqm = Ssm + 256;
    const float* sdx = (const float*)(sm+DX);
    const float* Wx  = (const float*)(sm+WX);
    float* Y = (LAYER==0) ? g_y0 : g_y1;

#pragma unroll
    for (int half = 0; half < NHALF; half++) {
        const int n0h = half*64;
        float acc[2][8][4];
#pragma unroll
        for (int mt=0; mt<2; mt++)
#pragma unroll
            for (int nt=0; nt<8; nt++)
#pragma unroll
                for (int j=0; j<4; j++) acc[mt][nt][j] = 0.f;

#pragma unroll
        for (int ks=0; ks<4; ks++) {
            const u32 kb = (u32)(ks*32);
            u32 Ah[2][4], Al[2][4];
#pragma unroll
            for (int mt=0; mt<2; mt++) {
                u32 row = (u32)(w*32 + mt*16) + aRowSel;
                u32 col = (kb + aKSel) ^ ((row&7)<<4);
                u32 adr = sbase + A_HI + row*128 + col;
                LDSM_X4(Ah[mt][0], Ah[mt][1], Ah[mt][2], Ah[mt][3], adr);
                LDSM_X4(Al[mt][0], Al[mt][1], Al[mt][2], Al[mt][3], adr + (u32)(A_LO - A_HI));
            }
#pragma unroll
            for (int ntp=0; ntp<4; ntp++) {
                u32 nrow = (u32)(n0h + ntp*16) + bNSel;
                u32 col  = (kb + bKSel) ^ ((nrow&7)<<4);
                u32 badr = sbase + B_HI + nrow*128 + col;
                u32 bh0, bh1, bh2, bh3, bl0, bl1, bl2, bl3;
                LDSM_X4(bh0, bh1, bh2, bh3, badr);
                LDSM_X4(bl0, bl1, bl2, bl3, badr + (u32)(B_LO - B_HI));
#pragma unroll
                for (int mt=0; mt<2; mt++) {
                    MMA_BF16(acc[mt][2*ntp],   Ah[mt], bh0, bh1);
                    MMA_BF16(acc[mt][2*ntp],   Ah[mt], bl0, bl1);
                    MMA_BF16(acc[mt][2*ntp],   Al[mt], bh0, bh1);
                    MMA_BF16(acc[mt][2*ntp+1], Ah[mt], bh2, bh3);
                    MMA_BF16(acc[mt][2*ntp+1], Ah[mt], bl2, bl3);
                    MMA_BF16(acc[mt][2*ntp+1], Al[mt], bh2, bh3);
                }
            }
        }
        __syncthreads();   // L0/L1: A free -> scratch; L2: order prev reads vs writes

#pragma unroll
        for (int nt=0; nt<8; nt++) {
            float y[2][4];
#pragma unroll
            for (int mt=0; mt<2; mt++)
#pragma unroll
                for (int j=0; j<4; j++) y[mt][j] = acc[mt][nt][j];
            if (LAYER == 0) {
#pragma unroll
                for (int mt=0; mt<2; mt++)
#pragma unroll
                    for (int j=0; j<4; j++) {
                        int r = w*32 + mt*16 + qr + ((j>>1)<<3);
                        int ch = nt*8 + qc*2 + (j&1);
                        y[mt][j] = fmaf(sdx[r], Wx[ch],
                                   fmaf(sdx[128+r], Wx[64+ch],
                                   fmaf(sdx[256+r], Wx[128+ch], y[mt][j])));
                    }
            }
            float s0 = y[0][0]+y[0][2]+y[1][0]+y[1][2];
            float s1 = y[0][1]+y[0][3]+y[1][1]+y[1][3];
            float q0 = y[0][0]*y[0][0]+y[0][2]*y[0][2]+y[1][0]*y[1][0]+y[1][2]*y[1][2];
            float q1 = y[0][1]*y[0][1]+y[0][3]*y[0][3]+y[1][1]*y[1][1]+y[1][3]*y[1][3];
            float mx0 = 0.f, mx1 = 0.f;
            if (LAYER == 2) {
                mx0 = fmaxf(fmaxf(y[0][0],y[0][2]), fmaxf(y[1][0],y[1][2]));
                mx1 = fmaxf(fmaxf(y[0][1],y[0][3]), fmaxf(y[1][1],y[1][3]));
            }
#pragma unroll
            for (int o=16; o>=4; o>>=1) {
                s0 += __shfl_down_sync(0xffffffffu, s0, o);
                s1 += __shfl_down_sync(0xffffffffu, s1, o);
                q0 += __shfl_down_sync(0xffffffffu, q0, o);
                q1 += __shfl_down_sync(0xffffffffu, q1, o);
                if (LAYER == 2) {
                    mx0 = fmaxf(mx0, __shfl_down_sync(0xffffffffu, mx0, o));
                    mx1 = fmaxf(mx1, __shfl_down_sync(0xffffffffu, mx1, o));
                }
            }
            if (lane < 4) {
                int ch = nt*8 + lane*2;
                Ssm[w*64 + ch] = s0;  Ssm[w*64 + ch + 1] = s1;
                Sqm[w*64 + ch] = q0;  Sqm[w*64 + ch + 1] = q1;
                if (LAYER == 2)
                    *(float2*)(g_gmax + ((size_t)(m0p>>5) + w)*128 + n0h + ch) = make_float2(mx0, mx1);
            }
            if (LAYER != 2) {
#pragma unroll
                for (int mt=0; mt<2; mt++) {
                    int r = m0p + w*32 + mt*16 + qr;
                    int ch = nt*8 + qc*2;
                    *(float2*)(Y + (size_t)r*64 + ch)     = make_float2(y[mt][0], y[mt][1]);
                    *(float2*)(Y + (size_t)(r+8)*64 + ch) = make_float2(y[mt][2], y[mt][3]);
                }
            }
        }
        __syncthreads();
        if (t < 64) {
            float vs = Ssm[t] + Ssm[64+t] + Ssm[128+t] + Ssm[192+t];
            float vq = Sqm[t] + Sqm[64+t] + Sqm[128+t] + Sqm[192+t];
            size_t pi = (LAYER==2) ? ((size_t)blockIdx.x*128 + n0h + t)
                                   : ((size_t)blockIdx.x*64 + t);
            g_parts[pi] = vs;
            g_partq[pi] = vq;
        }
    }
}

// ============================================================================
// 4) finalize BN (unchanged)
// ============================================================================
template <int C>
__global__ __launch_bounds__(256)
void finalize_kernel(const float* __restrict__ g, const float* __restrict__ be)
{
    __shared__ double shs[256], shq[256];
    const int c = blockIdx.x, t = threadIdx.x;
    double s = 0.0, q = 0.0;
    for (int i = t; i < 4096; i += 256) {
        s += (double)g_parts[(size_t)i * C + c];
        q += (double)g_partq[(size_t)i * C + c];
    }
    shs[t] = s; shq[t] = q;
    __syncthreads();
    for (int o = 128; o; o >>= 1) {
        if (t < o) { shs[t] += shs[t+o]; shq[t] += shq[t+o]; }
        __syncthreads();
    }
    if (t == 0) {
        double mean = shs[0] / (double)Mm;
        double var  = shq[0] / (double)Mm - mean * mean;
        float sc = g[c] * (1.0f / sqrtf((float)var + 1e-5f));
        g_scale[c] = sc;
        g_shift[c] = fmaf(-(float)mean, sc, be[c]);
    }
}

// ============================================================================
// 5) output (unchanged)
// ============================================================================
__global__ __launch_bounds__(256)
void maxout_kernel(float* __restrict__ feats)
{
    int i = blockIdx.x * 256 + threadIdx.x;
    int c = i & 127;
    feats[i] = fmaxf(fmaf(g_gmax[i], g_scale[c], g_shift[c]), 0.f);
}

// ============================================================================
extern "C" void kernel_launch(void* const* d_in, const int* in_sizes, int n_in,
                              void* d_out, int out_size)
{
    const float* xyz = (const float*)d_in[0];
    const float* fea = (const float*)d_in[1];
    const float* W0  = (const float*)d_in[2];
    const float* g0  = (const float*)d_in[4];
    const float* be0 = (const float*)d_in[5];
    const float* W1  = (const float*)d_in[6];
    const float* g1  = (const float*)d_in[8];
    const float* be1 = (const float*)d_in[9];
    const float* W2  = (const float*)d_in[10];
    const float* g2  = (const float*)d_in[12];
    const float* be2 = (const float*)d_in[13];

    float* out   = (float*)d_out;
    float* samp  = out;
    float* feats = out + Bb * Ss * 3;

    const int fps_smem = Nn*16 + 2*32*8;
    const int knn_smem = Nn*16;
    const int s01 = 51968;          // L0/L1: A32K B16K + DX/WX/IDX
    const int s2  = 65536 + 2048;   // L2:    A32K B32K + scratch

    cudaFuncSetAttribute(fps_kernel, cudaFuncAttributeMaxDynamicSharedMemorySize, fps_smem);
    cudaFuncSetAttribute(knn_kernel, cudaFuncAttributeMaxDynamicSharedMemorySize, knn_smem);
    cudaFuncSetAttribute(mma_kernel<0>, cudaFuncAttributeMaxDynamicSharedMemorySize, s01);
    cudaFuncSetAttribute(mma_kernel<1>, cudaFuncAttributeMaxDynamicSharedMemorySize, s01);
    cudaFuncSetAttribute(mma_kernel<2>, cudaFuncAttributeMaxDynamicSharedMemorySize, s2);

    // slots: prep(0), dummy(1), dummy(2) -> fps on capture slot 3
    prep_kernel<<<16, 256>>>(W0, W1, W2);
    dummy_kernel<<<1, 32>>>();
    dummy_kernel<<<1, 32>>>();

    fps_kernel<<<Bb, 1024, fps_smem>>>(xyz, samp);
    knn_kernel<<<dim3(Ss/16, Bb), 512, knn_smem>>>(xyz, samp);

    mma_kernel<0><<<Mm/128, 128, s01>>>(fea, xyz, samp);
    finalize_kernel<64><<<64, 256>>>(g0, be0);

    mma_kernel<1><<<Mm/128, 128, s01>>>(nullptr, nullptr, nullptr);
    finalize_kernel<64><<<64, 256>>>(g1, be1);

    mma_kernel<2><<<Mm/128, 128, s2>>>(nullptr, nullptr, nullptr);
    finalize_kernel<128><<<128, 256>>>(g2, be2);

    maxout_kernel<<<(Bb*Ss*128)/256, 256>>>(feats);
}

// round 17
// speedup vs baseline: 1.0701x; 1.0701x over previous
#include <cuda_runtime.h>
#include <cuda_bf16.h>
#include <math.h>

#define Bb 16
#define Nn 4096
#define Dd 64
#define Ss 1024
#define Kk 32
#define Mm (Bb*Ss*Kk)

typedef unsigned long long ull;
typedef unsigned int u32;
typedef unsigned short u16;

__device__ int    g_knn[Mm];
__device__ float  g_y0[Mm*64];
__device__ float  g_y1[Mm*64];
__device__ float  g_parts[4096*128];
__device__ float  g_partq[4096*128];
__device__ float  g_gmax[Bb*Ss*128];
__device__ float  g_scale[128];
__device__ float  g_shift[128];
__device__ __align__(16) u16 g_Bh[3][8192];
__device__ __align__(16) u16 g_Bl[3][8192];
__device__ float  g_W0xyz[192];
__device__ int    g_dummy;

// ---- f32x2 helpers (fps) ----
__device__ __forceinline__ ull f2add(ull a, ull b){ ull d; asm("add.rn.f32x2 %0,%1,%2;":"=l"(d):"l"(a),"l"(b)); return d; }
__device__ __forceinline__ ull f2mul(ull a, ull b){ ull d; asm("mul.rn.f32x2 %0,%1,%2;":"=l"(d):"l"(a),"l"(b)); return d; }
__device__ __forceinline__ ull f2dup(float v){ ull d; asm("mov.b64 %0,{%1,%1};":"=l"(d):"f"(v)); return d; }
__device__ __forceinline__ ull f2pack(float l, float h){ ull d; asm("mov.b64 %0,{%1,%2};":"=l"(d):"f"(l),"f"(h)); return d; }
__device__ __forceinline__ void f2unpack(ull v, float& l, float& h){ asm("mov.b64 {%0,%1},%2;":"=f"(l),"=f"(h):"l"(v)); }
__device__ __forceinline__ unsigned mono(float f){ unsigned b=__float_as_uint(f); return b ^ (unsigned)(((int)b>>31)|0x80000000); }

__device__ __forceinline__ u32 bfpack(float a, float b){
    __nv_bfloat16 ha=__float2bfloat16(a), hb=__float2bfloat16(b);
    return (u32)(*(u16*)&ha) | ((u32)(*(u16*)&hb)<<16);
}
__device__ __forceinline__ u32 s2u(const void* p){
    u32 a; asm("{ .reg .u64 t; cvta.to.shared.u64 t, %1; cvt.u32.u64 %0, t; }":"=r"(a):"l"(p)); return a;
}

#define MMA_BF16(c, a, b0v, b1v) \
    asm volatile("mma.sync.aligned.m16n8k16.row.col.f32.bf16.bf16.f32 " \
        "{%0,%1,%2,%3},{%4,%5,%6,%7},{%8,%9},{%0,%1,%2,%3};" \
        : "+f"((c)[0]),"+f"((c)[1]),"+f"((c)[2]),"+f"((c)[3]) \
        : "r"((a)[0]),"r"((a)[1]),"r"((a)[2]),"r"((a)[3]), "r"(b0v),"r"(b1v))

#define LDSM_X4(r0,r1,r2,r3,addr) \
    asm volatile("ldmatrix.sync.aligned.m8n8.x4.shared.b16 {%0,%1,%2,%3}, [%4];" \
        : "=r"(r0),"=r"(r1),"=r"(r2),"=r"(r3) : "r"(addr))

// ============================================================================
// 0) prep + one dummy (capture slot 3 = knn)
// ============================================================================
__device__ __forceinline__ void wsplit(float x, u16* H, u16* L, int o, int k){
    __nv_bfloat16 h = __float2bfloat16(x);
    float r = x - __bfloat162float(h);
    __nv_bfloat16 l = __float2bfloat16(r);
    u32 off = (u32)(o*128) + (((u32)(k*2)) ^ (u32)((o&7)<<4));
    H[off>>1] = *(u16*)&h;  L[off>>1] = *(u16*)&l;
}
__global__ void prep_kernel(const float* __restrict__ W0, const float* __restrict__ W1,
                            const float* __restrict__ W2){
    int t = blockIdx.x*256+threadIdx.x, st = gridDim.x*256;
    for (int i=t;i<4096;i+=st){ int o=i>>6,k=i&63; wsplit(W0[o*67+3+k], g_Bh[0], g_Bl[0], o,k); }
    for (int i=t;i<4096;i+=st){ int o=i>>6,k=i&63; wsplit(W1[o*64+k],   g_Bh[1], g_Bl[1], o,k); }
    for (int i=t;i<8192;i+=st){ int o=i>>6,k=i&63; wsplit(W2[o*64+k],   g_Bh[2], g_Bl[2], o,k); }
    for (int i=t;i<192;i+=st){ int j=i>>6,o=i&63; g_W0xyz[j*64+o] = W0[o*67+j]; }
}
__global__ void dummy_kernel(){ if (threadIdx.x == 1024) g_dummy = 1; }

// ============================================================================
// 1) FPS: 512 threads x 8 points (measured best). Bit-exact; 1 barrier/iter.
// ============================================================================
__global__ __launch_bounds__(512, 1)
void fps_kernel(const float* __restrict__ xyz, float* __restrict__ out_xyz)
{
    extern __shared__ float4 sp[];
    ull* s_key = (ull*)(sp + Nn);                  // [2][16]
    const int b = blockIdx.x, tid = threadIdx.x;
    const int lane = tid & 31, warp = tid >> 5;
    const float* base = xyz + (size_t)b * Nn * 3;

    ull px2[4], py2[4], pz2[4];
    float dist[8];
#pragma unroll
    for (int j = 0; j < 4; j++) {
        int plo = tid + (2*j)*512, phi = tid + (2*j+1)*512;
        float Xl = base[plo*3+0], Yl = base[plo*3+1], Zl = base[plo*3+2];
        float Xh = base[phi*3+0], Yh = base[phi*3+1], Zh = base[phi*3+2];
        sp[plo] = make_float4(Xl, Yl, Zl, 0.f);
        sp[phi] = make_float4(Xh, Yh, Zh, 0.f);
        px2[j] = f2pack(Xl, Xh); py2[j] = f2pack(Yl, Yh); pz2[j] = f2pack(Zl, Zh);
        dist[2*j] = 1e10f; dist[2*j+1] = 1e10f;
    }
    __syncthreads();

    int far = 0;
    float* ob = out_xyz + (size_t)b * Ss * 3;
    for (int it = 0; it < Ss; ++it) {
        float4 c = sp[far];
        if (tid == 0) { ob[it*3+0]=c.x; ob[it*3+1]=c.y; ob[it*3+2]=c.z; }
        ull ncx = f2dup(-c.x), ncy = f2dup(-c.y), ncz = f2dup(-c.z);
        unsigned u[8];
#pragma unroll
        for (int j = 0; j < 4; j++) {
            ull dx = f2add(px2[j], ncx), dy = f2add(py2[j], ncy), dz = f2add(pz2[j], ncz);
            ull s = f2add(f2add(f2mul(dx,dx), f2mul(dy,dy)), f2mul(dz,dz));
            float lo, hi; f2unpack(s, lo, hi);
            float dl = fminf(dist[2*j], lo), dh = fminf(dist[2*j+1], hi);
            dist[2*j] = dl; dist[2*j+1] = dh;
            u[2*j] = __float_as_uint(dl); u[2*j+1] = __float_as_uint(dh);
        }
        unsigned v[4], jx[4];
#pragma unroll
        for (int j = 0; j < 4; j++) {
            bool g = u[2*j+1] > u[2*j];
            v[j] = g ? u[2*j+1] : u[2*j];
            jx[j] = 2*j + (g ? 1u : 0u);
        }
        bool ga = v[1] > v[0];
        unsigned va = ga ? v[1] : v[0], ja = ga ? jx[1] : jx[0];
        bool gb = v[3] > v[2];
        unsigned vb2 = gb ? v[3] : v[2], jb = gb ? jx[3] : jx[2];
        bool gc = vb2 > va;
        unsigned bb = gc ? vb2 : va, jj = gc ? jb : ja;
        int bi = tid + (int)jj * 512;

        unsigned mv = __reduce_max_sync(0xffffffffu, bb);
        int ci = (bb == mv) ? bi : 0x7fffffff;
        int mi = __reduce_min_sync(0xffffffffu, ci);
        if (lane == 0)
            s_key[(it&1)*16 + warp] = ((ull)mv << 32) | (unsigned)(0x7fffffff - mi);
        __syncthreads();
        ull k = s_key[(it&1)*16 + (lane & 15)];
        unsigned hv = (unsigned)(k >> 32), lv = (unsigned)k;
        unsigned mh = __reduce_max_sync(0xffffffffu, hv);
        unsigned ml = __reduce_max_sync(0xffffffffu, (hv == mh) ? lv : 0u);
        far = 0x7fffffff - (int)ml;
    }
}

// ============================================================================
// 2) KNN: warp per query, single pass
// ============================================================================
__global__ __launch_bounds__(512, 1)
void knn_kernel(const float* __restrict__ xyz, const float* __restrict__ samp)
{
    extern __shared__ float4 sq[];
    const int b = blockIdx.y, t = threadIdx.x;
    const int lane = t & 31, w = t >> 5;
    const float* base = xyz + (size_t)b * Nn * 3;
    for (int j = t; j < Nn; j += 512) {
        float x = base[j*3], y = base[j*3+1], z = base[j*3+2];
        sq[j] = make_float4(x, y, z, fmaf(x,x, fmaf(y,y, z*z)));
    }
    __syncthreads();

    const int q = b * Ss + blockIdx.x * 16 + w;
    float qx = samp[q*3], qy = samp[q*3+1], qz = samp[q*3+2];
    float ax = -2.0f*qx, ay = -2.0f*qy, az = -2.0f*qz;

    float4 p0 = sq[lane];
    unsigned held = mono(fmaf(az, p0.z, fmaf(ay, p0.y, fmaf(ax, p0.x, p0.w))));
    int held_idx = lane;
    unsigned thr = __reduce_max_sync(0xffffffffu, held);

#pragma unroll 1
    for (int step = 1; step < Nn/32; step++) {
        float4 p = sq[step*32 + lane];
        unsigned u = mono(fmaf(az, p.z, fmaf(ay, p.y, fmaf(ax, p.x, p.w))));
        unsigned m = __ballot_sync(0xffffffffu, u < thr);
        while (m) {
            int src = __ffs(m) - 1;
            unsigned uc = __shfl_sync(0xffffffffu, u, src);
            if (uc < thr) {
                unsigned vb = __ballot_sync(0xffffffffu, held == thr);
                int victim = __ffs(vb) - 1;
                if (lane == victim) { held = uc; held_idx = step*32 + src; }
                thr = __reduce_max_sync(0xffffffffu, held);
            }
            m &= m - 1;
            m &= __ballot_sync(0xffffffffu, u < thr);
        }
    }
    g_knn[(size_t)q * Kk + lane] = held_idx;
}

// ============================================================================
// 3) MLP layer: 128 threads, 4 warps x 32-row tiles, bf16-split mma.sync.
//    L0/L1: STS-based stats epilogue (no shuffle trees). L2: single pass over
//    both 64-ch halves, shuffle epilogue (A must survive across halves).
// ============================================================================
template <int LAYER>
__global__ __launch_bounds__(128)
void mma_kernel(const float* __restrict__ fea, const float* __restrict__ xyz,
                const float* __restrict__ samp)
{
    constexpr int NB    = (LAYER==2) ? 128 : 64;
    constexpr int NHALF = NB/64;
    constexpr int A_HI=0, A_LO=16384, B_HI=32768;
    constexpr int B_LO = B_HI + NB*128;
    constexpr int SCR  = (LAYER==2) ? (B_LO + NB*128) : 0;
    constexpr int DX=49152, WX=50688, IDX=51456;             // layer0 only

    extern __shared__ __align__(16) char sm[];
    const int t = threadIdx.x, lane = t&31, w = t>>5;
    const int m0p = blockIdx.x*128;

    {
        const uint4* BH = (const uint4*)(g_Bh[LAYER]);
        const uint4* BL = (const uint4*)(g_Bl[LAYER]);
        uint4* dh = (uint4*)(sm+B_HI); uint4* dl = (uint4*)(sm+B_LO);
        for (int i = t; i < NB*8; i += 128) { dh[i] = BH[i]; dl[i] = BL[i]; }
    }

    const int rloc0 = w*32 + (lane>>4);
    const int cc = (lane & 15)*4;
    if (LAYER == 0) {
        int m = m0p + t, g = m>>5, idx = g_knn[m];
        int row = (g>>10)*Nn + idx;
        ((int*)(sm+IDX))[t] = row;
        ((float*)(sm+DX))[t]     = xyz[row*3+0]-samp[g*3+0];
        ((float*)(sm+DX))[128+t] = xyz[row*3+1]-samp[g*3+1];
        ((float*)(sm+DX))[256+t] = xyz[row*3+2]-samp[g*3+2];
        for (int i=t;i<192;i+=128) ((float*)(sm+WX))[i] = g_W0xyz[i];
        __syncthreads();
#pragma unroll 4
        for (int it2 = 0; it2 < 16; it2++) {
            int rr = rloc0 + it2*2;
            int gr = ((const int*)(sm+IDX))[rr];
            float4 v = *(const float4*)(fea + (size_t)gr*Dd + cc);
            u32 sw = (u32)((rr&7)<<4);
            __nv_bfloat16 h0=__float2bfloat16(v.x), h1=__float2bfloat16(v.y);
            __nv_bfloat16 h2=__float2bfloat16(v.z), h3=__float2bfloat16(v.w);
            u32 o0 = ((u32)(cc*2)) ^ sw;
            *(u32*)(sm+A_HI + rr*128 + o0)   = (u32)(*(u16*)&h0) | ((u32)(*(u16*)&h1)<<16);
            *(u32*)(sm+A_HI + rr*128 + o0+4) = (u32)(*(u16*)&h2) | ((u32)(*(u16*)&h3)<<16);
            *(u32*)(sm+A_LO + rr*128 + o0)   = bfpack(v.x-__bfloat162float(h0), v.y-__bfloat162float(h1));
            *(u32*)(sm+A_LO + rr*128 + o0+4) = bfpack(v.z-__bfloat162float(h2), v.w-__bfloat162float(h3));
        }
    } else {
        const float* Xin = (LAYER==1) ? g_y0 : g_y1;
        const float sc0 = g_scale[cc],   sh0 = g_shift[cc];
        const float sc1 = g_scale[cc+1], sh1 = g_shift[cc+1];
        const float sc2 = g_scale[cc+2], sh2 = g_shift[cc+2];
        const float sc3 = g_scale[cc+3], sh3 = g_shift[cc+3];
#pragma unroll 4
        for (int it2 = 0; it2 < 16; it2++) {
            int rr = rloc0 + it2*2;
            float4 v = *(const float4*)(Xin + (size_t)(m0p+rr)*64 + cc);
            float x0 = fmaxf(fmaf(v.x, sc0, sh0), 0.f);
            float x1 = fmaxf(fmaf(v.y, sc1, sh1), 0.f);
            float x2 = fmaxf(fmaf(v.z, sc2, sh2), 0.f);
            float x3 = fmaxf(fmaf(v.w, sc3, sh3), 0.f);
            u32 sw = (u32)((rr&7)<<4);
            __nv_bfloat16 h0=__float2bfloat16(x0), h1=__float2bfloat16(x1);
            __nv_bfloat16 h2=__float2bfloat16(x2), h3=__float2bfloat16(x3);
            u32 o0 = ((u32)(cc*2)) ^ sw;
            *(u32*)(sm+A_HI + rr*128 + o0)   = (u32)(*(u16*)&h0) | ((u32)(*(u16*)&h1)<<16);
            *(u32*)(sm+A_HI + rr*128 + o0+4) = (u32)(*(u16*)&h2) | ((u32)(*(u16*)&h3)<<16);
            *(u32*)(sm+A_LO + rr*128 + o0)   = bfpack(x0-__bfloat162float(h0), x1-__bfloat162float(h1));
            *(u32*)(sm+A_LO + rr*128 + o0+4) = bfpack(x2-__bfloat162float(h2), x3-__bfloat162float(h3));
        }
    }
    __syncthreads();

    const u32 sbase = s2u(sm);
    const int qr = lane>>2, qc = lane&3;
    const u32 aRowSel = (u32)(((lane>>3)&1)*8 + (lane&7));
    const u32 aKSel   = (u32)((lane>>4)*16);
    const u32 bNSel   = (u32)((lane>>4)*8 + (lane&7));
    const u32 bKSel   = (u32)(((lane>>3)&1)*16);

    const float* sdx = (const float*)(sm+DX);
    const float* Wx  = (const float*)(sm+WX);
    float* Y = (LAYER==0) ? g_y0 : g_y1;

#pragma unroll
    for (int half = 0; half < NHALF; half++) {
        const int n0h = half*64;
        float acc[2][8][4];
#pragma unroll
        for (int mt=0; mt<2; mt++)
#pragma unroll
            for (int nt=0; nt<8; nt++)
#pragma unroll
                for (int j=0; j<4; j++) acc[mt][nt][j] = 0.f;

#pragma unroll
        for (int ks=0; ks<4; ks++) {
            const u32 kb = (u32)(ks*32);
            u32 Ah[2][4], Al[2][4];
#pragma unroll
            for (int mt=0; mt<2; mt++) {
                u32 row = (u32)(w*32 + mt*16) + aRowSel;
                u32 col = (kb + aKSel) ^ ((row&7)<<4);
                u32 adr = sbase + A_HI + row*128 + col;
                LDSM_X4(Ah[mt][0], Ah[mt][1], Ah[mt][2], Ah[mt][3], adr);
                LDSM_X4(Al[mt][0], Al[mt][1], Al[mt][2], Al[mt][3], adr + (u32)(A_LO - A_HI));
            }
#pragma unroll
            for (int ntp=0; ntp<4; ntp++) {
                u32 nrow = (u32)(n0h + ntp*16) + bNSel;
                u32 col  = (kb + bKSel) ^ ((nrow&7)<<4);
                u32 badr = sbase + B_HI + nrow*128 + col;
                u32 bh0, bh1, bh2, bh3, bl0, bl1, bl2, bl3;
                LDSM_X4(bh0, bh1, bh2, bh3, badr);
                LDSM_X4(bl0, bl1, bl2, bl3, badr + (u32)(B_LO - B_HI));
#pragma unroll
                for (int mt=0; mt<2; mt++) {
                    MMA_BF16(acc[mt][2*ntp],   Ah[mt], bh0, bh1);
                    MMA_BF16(acc[mt][2*ntp],   Ah[mt], bl0, bl1);
                    MMA_BF16(acc[mt][2*ntp],   Al[mt], bh0, bh1);
                    MMA_BF16(acc[mt][2*ntp+1], Ah[mt], bh2, bh3);
                    MMA_BF16(acc[mt][2*ntp+1], Ah[mt], bl2, bl3);
                    MMA_BF16(acc[mt][2*ntp+1], Al[mt], bh2, bh3);
                }
            }
        }
        __syncthreads();

        if (LAYER != 2) {
            // ---- STS-based stats epilogue (A region reused as [32][65] x2) ----
            float* Sp = (float*)sm;          // [32][65]
            float* Qp = Sp + 2080;           // [32][65]
            const int r32 = w*8 + qr;
#pragma unroll
            for (int nt=0; nt<8; nt++) {
                float y[2][4];
#pragma unroll
                for (int mt=0; mt<2; mt++)
#pragma unroll
                    for (int j=0; j<4; j++) y[mt][j] = acc[mt][nt][j];
                if (LAYER == 0) {
#pragma unroll
                    for (int mt=0; mt<2; mt++)
#pragma unroll
                        for (int j=0; j<4; j++) {
                            int r = w*32 + mt*16 + qr + ((j>>1)<<3);
                            int ch = nt*8 + qc*2 + (j&1);
                            y[mt][j] = fmaf(sdx[r], Wx[ch],
                                       fmaf(sdx[128+r], Wx[64+ch],
                                       fmaf(sdx[256+r], Wx[128+ch], y[mt][j])));
                        }
                }
                float s0 = y[0][0]+y[0][2]+y[1][0]+y[1][2];
                float s1 = y[0][1]+y[0][3]+y[1][1]+y[1][3];
                float q0 = y[0][0]*y[0][0]+y[0][2]*y[0][2]+y[1][0]*y[1][0]+y[1][2]*y[1][2];
                float q1 = y[0][1]*y[0][1]+y[0][3]*y[0][3]+y[1][1]*y[1][1]+y[1][3]*y[1][3];
                int ch = nt*8 + qc*2;
                Sp[r32*65 + ch]   = s0;  Sp[r32*65 + ch+1] = s1;
                Qp[r32*65 + ch]   = q0;  Qp[r32*65 + ch+1] = q1;
#pragma unroll
                for (int mt=0; mt<2; mt++) {
                    int r = m0p + w*32 + mt*16 + qr;
                    *(float2*)(Y + (size_t)r*64 + ch)     = make_float2(y[mt][0], y[mt][1]);
                    *(float2*)(Y + (size_t)(r+8)*64 + ch) = make_float2(y[mt][2], y[mt][3]);
                }
            }
            __syncthreads();
            if (t < 64) {
                float vs = 0.f, vq = 0.f;
#pragma unroll
                for (int r = 0; r < 32; r++) {
                    vs += Sp[r*65 + t];
                    vq += Qp[r*65 + t];
                }
                g_parts[(size_t)blockIdx.x*64 + t] = vs;
                g_partq[(size_t)blockIdx.x*64 + t] = vq;
            }
        } else {
            // ---- L2: shuffle epilogue + group max (scratch above B) ----
            float* Ssm = (float*)(sm + SCR);
            float* Sqm = Ssm + 256;
#pragma unroll
            for (int nt=0; nt<8; nt++) {
                float y[2][4];
#pragma unroll
                for (int mt=0; mt<2; mt++)
#pragma unroll
                    for (int j=0; j<4; j++) y[mt][j] = acc[mt][nt][j];
                float s0 = y[0][0]+y[0][2]+y[1][0]+y[1][2];
                float s1 = y[0][1]+y[0][3]+y[1][1]+y[1][3];
                float q0 = y[0][0]*y[0][0]+y[0][2]*y[0][2]+y[1][0]*y[1][0]+y[1][2]*y[1][2];
                float q1 = y[0][1]*y[0][1]+y[0][3]*y[0][3]+y[1][1]*y[1][1]+y[1][3]*y[1][3];
                float mx0 = fmaxf(fmaxf(y[0][0],y[0][2]), fmaxf(y[1][0],y[1][2]));
                float mx1 = fmaxf(fmaxf(y[0][1],y[0][3]), fmaxf(y[1][1],y[1][3]));
#pragma unroll
                for (int o=16; o>=4; o>>=1) {
                    s0 += __shfl_down_sync(0xffffffffu, s0, o);
                    s1 += __shfl_down_sync(0xffffffffu, s1, o);
                    q0 += __shfl_down_sync(0xffffffffu, q0, o);
                    q1 += __shfl_down_sync(0xffffffffu, q1, o);
                    mx0 = fmaxf(mx0, __shfl_down_sync(0xffffffffu, mx0, o));
                    mx1 = fmaxf(mx1, __shfl_down_sync(0xffffffffu, mx1, o));
                }
                if (lane < 4) {
                    int ch = nt*8 + lane*2;
                    Ssm[w*64 + ch] = s0;  Ssm[w*64 + ch + 1] = s1;
                    Sqm[w*64 + ch] = q0;  Sqm[w*64 + ch + 1] = q1;
                    *(float2*)(g_gmax + ((size_t)(m0p>>5) + w)*128 + n0h + ch) = make_float2(mx0, mx1);
                }
            }
            __syncthreads();
            if (t < 64) {
                float vs = Ssm[t] + Ssm[64+t] + Ssm[128+t] + Ssm[192+t];
                float vq = Sqm[t] + Sqm[64+t] + Sqm[128+t] + Sqm[192+t];
                g_parts[(size_t)blockIdx.x*128 + n0h + t] = vs;
                g_partq[(size_t)blockIdx.x*128 + n0h + t] = vq;
            }
        }
    }
}

// ============================================================================
// 4) finalize BN
// ============================================================================
template <int C>
__global__ __launch_bounds__(256)
void finalize_kernel(const float* __restrict__ g, const float* __restrict__ be)
{
    __shared__ double shs[256], shq[256];
    const int c = blockIdx.x, t = threadIdx.x;
    double s = 0.0, q = 0.0;
    for (int i = t; i < 4096; i += 256) {
        s += (double)g_parts[(size_t)i * C + c];
        q += (double)g_partq[(size_t)i * C + c];
    }
    shs[t] = s; shq[t] = q;
    __syncthreads();
    for (int o = 128; o; o >>= 1) {
        if (t < o) { shs[t] += shs[t+o]; shq[t] += shq[t+o]; }
        __syncthreads();
    }
    if (t == 0) {
        double mean = shs[0] / (double)Mm;
        double var  = shq[0] / (double)Mm - mean * mean;
        float sc = g[c] * (1.0f / sqrtf((float)var + 1e-5f));
        g_scale[c] = sc;
        g_shift[c] = fmaf(-(float)mean, sc, be[c]);
    }
}

// ============================================================================
// 5) output
// ============================================================================
__global__ __launch_bounds__(256)
void maxout_kernel(float* __restrict__ feats)
{
    int i = blockIdx.x * 256 + threadIdx.x;
    int c = i & 127;
    feats[i] = fmaxf(fmaf(g_gmax[i], g_scale[c], g_shift[c]), 0.f);
}

// ============================================================================
extern "C" void kernel_launch(void* const* d_in, const int* in_sizes, int n_in,
                              void* d_out, int out_size)
{
    const float* xyz = (const float*)d_in[0];
    const float* fea = (const float*)d_in[1];
    const float* W0  = (const float*)d_in[2];
    const float* g0  = (const float*)d_in[4];
    const float* be0 = (const float*)d_in[5];
    const float* W1  = (const float*)d_in[6];
    const float* g1  = (const float*)d_in[8];
    const float* be1 = (const float*)d_in[9];
    const float* W2  = (const float*)d_in[10];
    const float* g2  = (const float*)d_in[12];
    const float* be2 = (const float*)d_in[13];

    float* out   = (float*)d_out;
    float* samp  = out;
    float* feats = out + Bb * Ss * 3;

    const int fps_smem = Nn*16 + 2*16*8;
    const int knn_smem = Nn*16;
    const int s01 = 51968;          // L0/L1: A32K B16K + DX/WX/IDX
    const int s2  = 65536 + 2048;   // L2:    A32K B32K + scratch

    cudaFuncSetAttribute(fps_kernel, cudaFuncAttributeMaxDynamicSharedMemorySize, fps_smem);
    cudaFuncSetAttribute(knn_kernel, cudaFuncAttributeMaxDynamicSharedMemorySize, knn_smem);
    cudaFuncSetAttribute(mma_kernel<0>, cudaFuncAttributeMaxDynamicSharedMemorySize, s01);
    cudaFuncSetAttribute(mma_kernel<1>, cudaFuncAttributeMaxDynamicSharedMemorySize, s01);
    cudaFuncSetAttribute(mma_kernel<2>, cudaFuncAttributeMaxDynamicSharedMemorySize, s2);

    // slots: prep(0), dummy(1), fps(2) -> knn on capture slot 3
    prep_kernel<<<16, 256>>>(W0, W1, W2);
    dummy_kernel<<<1, 32>>>();

    fps_kernel<<<Bb, 512, fps_smem>>>(xyz, samp);
    knn_kernel<<<dim3(Ss/16, Bb), 512, knn_smem>>>(xyz, samp);

    mma_kernel<0><<<Mm/128, 128, s01>>>(fea, xyz, samp);
    finalize_kernel<64><<<64, 256>>>(g0, be0);

    mma_kernel<1><<<Mm/128, 128, s01>>>(nullptr, nullptr, nullptr);
    finalize_kernel<64><<<64, 256>>>(g1, be1);

    mma_kernel<2><<<Mm/128, 128, s2>>>(nullptr, nullptr, nullptr);
    finalize_kernel<128><<<128, 256>>>(g2, be2);

    maxout_kernel<<<(Bb*Ss*128)/256, 256>>>(feats);
}